// round 14
// baseline (speedup 1.0000x reference)
#include <cuda_runtime.h>
#include <cstdint>

// GCN layer via mma.sync tf32 (HMMA): N-half phases, merged dual-GEMM,
// 3-stage cp.async pipeline, one barrier per chunk, 512 threads (16 warps,
// 4M x 4N) for 4 warps/SMSP latency hiding.
// A operands: raw fp32 bits (HW tf32 truncation). B: rna-rounded in prepass.
// CTA = 128 rows (2 sentences); phase p covers cols p*128..+127.
// Warp tile 32x32 DUAL (P_in + P_self) -> 64 acc regs/thread.

#define BNK_   1280
#define L_     64
#define DIN_   512
#define DOUT_  256
#define KC     32
#define NCHUNK 16
#define NT     512

typedef unsigned int u32;

// Pre-transposed, tf32-rounded, SW128-swizzled W: [which][chunk][n=256][k=32]
__device__ float WT_sw[2][NCHUNK][DOUT_][KC];

// ---- SMEM byte offsets ----
#define OFF_GIN  0
#define OFF_GSF  512
#define OFF_WIN  1024
#define OFF_WSF  1536
#define OFF_MKV  2048
#define OFF_GLI  2560
#define OFF_LRI  3072
#define OFF_STG  4096
#define STG_STRIDE 49152          // A 16K + Bi 16K + Bs 16K
#define OFF_PIN  (OFF_STG + 3 * STG_STRIDE)    // 151552
#define SMEM_TOTAL (OFF_PIN + 65536)           // 217088

__device__ __forceinline__ u32 smem_u32(const void* p) {
    u32 a;
    asm("{ .reg .u64 t; cvta.to.shared.u64 t, %1; cvt.u32.u64 %0, t; }"
        : "=r"(a) : "l"(p));
    return a;
}
__device__ __forceinline__ void cpa16(u32 dst, const void* src) {
    asm volatile("cp.async.cg.shared.global [%0], [%1], 16;\n"
                 :: "r"(dst), "l"(src));
}

// A operands passed as raw u32 bits (tf32 = truncated fp32 in HW)
#define MMA8U(d, A, B0, B1)                                                   \
    asm volatile(                                                             \
        "mma.sync.aligned.m16n8k8.row.col.f32.tf32.tf32.f32 "                 \
        "{%0,%1,%2,%3}, {%4,%5,%6,%7}, {%8,%9}, {%0,%1,%2,%3};"               \
        : "+f"((d)[0]), "+f"((d)[1]), "+f"((d)[2]), "+f"((d)[3])              \
        : "r"((A)[0]), "r"((A)[1]), "r"((A)[2]), "r"((A)[3]),                 \
          "r"(B0), "r"(B1))

#define LDMX4(x0, x1, x2, x3, addr)                                           \
    asm volatile(                                                             \
        "ldmatrix.sync.aligned.m8n8.x4.shared.b16 {%0,%1,%2,%3}, [%4];"       \
        : "=r"(x0), "=r"(x1), "=r"(x2), "=r"(x3) : "r"(addr))

// -------------------- prepass: transpose + tf32-round W ---------------------
extern "C" __global__ void prep_wt(const float* __restrict__ W_in,
                                   const float* __restrict__ W_self)
{
    int idx = blockIdx.x * 256 + threadIdx.x;   // 0 .. 262143
    int which = idx >> 17;
    int rem = idx & 131071;
    int k = rem >> 8;        // 0..511 (coalesced reads over n)
    int n = rem & 255;
    const float* W = which ? W_self : W_in;
    float v = W[k * DOUT_ + n];
    asm("cvt.rna.tf32.f32 %0, %1;" : "=f"(v) : "f"(v));
    int c = k >> 5, kk = k & 31;
    int byte = n * 128 + kk * 4;
    int sw = byte ^ ((byte >> 3) & 0x70);
    *(float*)((char*)&WT_sw[which][c][0][0] + sw) = v;
}

// ------------------------------- main kernel --------------------------------
extern "C" __global__ void __launch_bounds__(NT, 1)
gcn_hmma(const float* __restrict__ rep,
         const float* __restrict__ adj_mask_in,
         const float* __restrict__ adj_mask_loop,
         const float* __restrict__ mask,
         const float* __restrict__ b_in,
         const float* __restrict__ bg_in,
         const float* __restrict__ Wg_in,
         const float* __restrict__ Wg_self,
         const int* __restrict__ arc,
         const int* __restrict__ lab,
         float* __restrict__ out)
{
    extern __shared__ char smem[];
    const u32 sb = smem_u32(smem);
    const int tid = threadIdx.x;
    const int ln = tid & 31;
    const int wid = tid >> 5;
    const int wm = wid >> 2;     // 0..3  (M quarter: 32 rows)
    const int wn = wid & 3;      // 0..3  (N quarter of 128: 32 cols)
    const int g = ln >> 2;
    const int t = ln & 3;
    const int m0 = blockIdx.x * 128;

    // ldmatrix lane-address components
    const int rowA = wm * 32 + (ln & 7) + ((ln >> 3) & 1) * 8;   // + mt*16
    const int koffA = ((ln >> 4) & 1) * 16;
    const int rowB = wn * 32 + ((ln >> 4) & 1) * 8 + (ln & 7);   // + nt2*16
    const int koffB = ((ln >> 3) & 1) * 16;

    // precomputed cp.async A-destination (swizzled) offsets: 1024 float4
    int arow[2], asw[2], aq[2];
#pragma unroll
    for (int i = 0; i < 2; i++) {
        int idx = tid + NT * i;
        arow[i] = idx >> 3;
        aq[i] = idx & 7;
        int b = arow[i] * 128 + aq[i] * 16;
        asw[i] = b ^ ((b >> 3) & 0x70);
    }

    // ch = global chunk 0..31; phase = ch>>4 selects N-half; kc = ch&15
#define LOAD_CHUNK(ch)                                                         \
    do {                                                                       \
        int kc_ = (ch) & 15, p_ = (ch) >> 4;                                   \
        u32 stg = sb + OFF_STG + ((ch) % 3) * STG_STRIDE;                      \
        const char* ab = (const char*)rep + (size_t)m0 * 2048 + kc_ * 128;     \
        _Pragma("unroll")                                                      \
        for (int i = 0; i < 2; i++)                                            \
            cpa16(stg + asw[i], ab + (size_t)arow[i] * 2048 + aq[i] * 16);     \
        const char* bi = (const char*)WT_sw + (size_t)kc_ * 32768              \
                       + p_ * 16384;                                           \
        const char* bs = bi + (size_t)NCHUNK * 32768;                          \
        _Pragma("unroll")                                                      \
        for (int i = 0; i < 2; i++) {                                          \
            int o = (tid + NT * i) * 16;                                       \
            cpa16(stg + 16384 + o, bi + o);                                    \
            cpa16(stg + 32768 + o, bs + o);                                    \
        }                                                                      \
        asm volatile("cp.async.commit_group;\n" ::: "memory");                 \
    } while (0)

    // prologue: chunks 0,1
    LOAD_CHUNK(0);
    LOAD_CHUNK(1);

    // ---------------- gate GEMVs (full fp32), overlap prologue --------------
    {
        int row = tid >> 2, part = tid & 3;  // 128 rows x 4 K-quarters
        const float4* rp = (const float4*)(rep + (size_t)(m0 + row) * DIN_ + part * 128);
        const float4* gi = (const float4*)(Wg_in + part * 128);
        const float4* gs = (const float4*)(Wg_self + part * 128);
        float ai = 0.f, as = 0.f;
#pragma unroll 8
        for (int q = 0; q < 32; q++) {
            float4 v = rp[q], wi = gi[q], ws = gs[q];
            ai += v.x * wi.x + v.y * wi.y + v.z * wi.z + v.w * wi.w;
            as += v.x * ws.x + v.y * ws.y + v.z * ws.z + v.w * ws.w;
        }
        ai += __shfl_xor_sync(0xffffffffu, ai, 1);
        ai += __shfl_xor_sync(0xffffffffu, ai, 2);
        as += __shfl_xor_sync(0xffffffffu, as, 1);
        as += __shfl_xor_sync(0xffffffffu, as, 2);
        if (part == 0) {
            ((float*)(smem + OFF_GIN))[row] = ai;
            ((float*)(smem + OFF_GSF))[row] = as;
        }
    }

    float acc_in[2][4][4];   // [mt][nt(n8 within 32 cols)][quad]
    float acc_sf[2][4][4];
#pragma unroll
    for (int mt = 0; mt < 2; mt++)
#pragma unroll
        for (int nt = 0; nt < 4; nt++)
#pragma unroll
            for (int q = 0; q < 4; q++) { acc_in[mt][nt][q] = 0.f; acc_sf[mt][nt][q] = 0.f; }

    // ------------------------------ main loop -------------------------------
    // iter c: wait(group c), sync, issue load c+2, compute c.
#pragma unroll 1
    for (int c = 0; c < 32; c++) {
        if (c < 31)
            asm volatile("cp.async.wait_group 1;" ::: "memory");
        else
            asm volatile("cp.async.wait_group 0;" ::: "memory");
        __syncthreads();

        if (c < 30) LOAD_CHUNK(c + 2);

        const u32 stg = sb + OFF_STG + (c % 3) * STG_STRIDE;
        const u32 aBase = stg, biBase = stg + 16384, bsBase = stg + 32768;
#pragma unroll
        for (int ks = 0; ks < 4; ks++) {
            u32 a[2][4];   // raw fp32 bits -> HW tf32 truncation
#pragma unroll
            for (int mt = 0; mt < 2; mt++) {
                int byte = (rowA + mt * 16) * 128 + ks * 32 + koffA;
                byte ^= (byte >> 3) & 0x70;
                LDMX4(a[mt][0], a[mt][1], a[mt][2], a[mt][3], aBase + byte);
            }
#pragma unroll
            for (int nt2 = 0; nt2 < 2; nt2++) {
                int byte = (rowB + nt2 * 16) * 128 + ks * 32 + koffB;
                byte ^= (byte >> 3) & 0x70;
                u32 b0, b1, b2, b3;
                LDMX4(b0, b1, b2, b3, biBase + byte);
                u32 e0, e1, e2, e3;
                LDMX4(e0, e1, e2, e3, bsBase + byte);
#pragma unroll
                for (int mt = 0; mt < 2; mt++) {
                    MMA8U(acc_in[mt][2 * nt2],     a[mt], b0, b1);
                    MMA8U(acc_sf[mt][2 * nt2],     a[mt], e0, e1);
                    MMA8U(acc_in[mt][2 * nt2 + 1], a[mt], b2, b3);
                    MMA8U(acc_sf[mt][2 * nt2 + 1], a[mt], e2, e3);
                }
            }
        }

        // ---------------- per-phase epilogue at c == 15 / 31 -----------------
        if ((c & 15) == 15) {
            const int p = c >> 4;
            const int cbase = p * 128;
            // stash P_in half-tile (128 x 128) to swizzled SMEM (own cells)
#pragma unroll
            for (int mt = 0; mt < 2; mt++)
#pragma unroll
                for (int nt = 0; nt < 4; nt++)
#pragma unroll
                    for (int h = 0; h < 2; h++) {
                        int r = wm * 32 + mt * 16 + g + h * 8;
                        int cc4 = (wn * 32 + nt * 8 + 2 * t) * 4;
                        u32 ad = sb + OFF_PIN + r * 512 + (cc4 ^ ((r & 7) << 4));
                        asm volatile("st.shared.v2.f32 [%0], {%1,%2};"
                                     :: "r"(ad), "f"(acc_in[mt][nt][2 * h]),
                                        "f"(acc_in[mt][nt][2 * h + 1]) : "memory");
                    }
            if (p == 0 && tid < 128) {   // per-row params, once
                int r = tid, m = m0 + r;
                int lr = lab[m];
                int gl = (arc[2 * m] * L_ + arc[2 * m + 1]) - m0;
                gl &= 127;
                float mi = adj_mask_in[m], mlp = adj_mask_loop[m];
                float giv = ((float*)(smem + OFF_GIN))[gl] + bg_in[lr];
                float gsv = ((float*)(smem + OFF_GSF))[r];
                ((float*)(smem + OFF_WIN))[r] = (1.f / (1.f + expf(-giv))) * mi * mi;
                ((float*)(smem + OFF_WSF))[r] = (1.f / (1.f + expf(-gsv))) * mlp * mlp;
                ((float*)(smem + OFF_MKV))[r] = mask[m];
                ((int*)(smem + OFF_GLI))[r] = gl;
                ((int*)(smem + OFF_LRI))[r] = lr;
            }
            __syncthreads();

            // combine: gather + gates + relu + store for this column half
#pragma unroll
            for (int mt = 0; mt < 2; mt++)
#pragma unroll
                for (int h = 0; h < 2; h++) {
                    int r = wm * 32 + mt * 16 + g + h * 8;
                    float w_in = ((float*)(smem + OFF_WIN))[r];
                    float w_sf = ((float*)(smem + OFF_WSF))[r];
                    float mkr = ((float*)(smem + OFF_MKV))[r];
                    int gl = ((int*)(smem + OFF_GLI))[r];
                    int lr = ((int*)(smem + OFF_LRI))[r];
                    const u32 pinrow = sb + OFF_PIN + gl * 512;
                    const int xr = (gl & 7) << 4;
                    const float* bb = b_in + lr * DOUT_ + cbase;
                    float* op = out + (size_t)(m0 + r) * DOUT_ + cbase;
#pragma unroll
                    for (int nt = 0; nt < 4; nt++) {
                        int cc = wn * 32 + nt * 8 + 2 * t;
                        float px, py;
                        asm volatile("ld.shared.v2.f32 {%0,%1}, [%2];"
                                     : "=f"(px), "=f"(py)
                                     : "r"(pinrow + ((cc * 4) ^ xr)));
                        float2 bv = *(const float2*)(bb + cc);
                        float2 o;
                        o.x = fmaxf((px + bv.x) * w_in + acc_sf[mt][nt][2 * h] * w_sf, 0.f) * mkr;
                        o.y = fmaxf((py + bv.y) * w_in + acc_sf[mt][nt][2 * h + 1] * w_sf, 0.f) * mkr;
                        *(float2*)(op + cc) = o;
                    }
                }

            if (p == 0) {  // reset accumulators for second half
#pragma unroll
                for (int mt = 0; mt < 2; mt++)
#pragma unroll
                    for (int nt = 0; nt < 4; nt++)
#pragma unroll
                        for (int q = 0; q < 4; q++) {
                            acc_in[mt][nt][q] = 0.f;
                            acc_sf[mt][nt][q] = 0.f;
                        }
            }
        }
    }
}

extern "C" void kernel_launch(void* const* d_in, const int* in_sizes, int n_in,
                              void* d_out, int out_size)
{
    (void)in_sizes; (void)n_in; (void)out_size;
    cudaFuncSetAttribute(gcn_hmma, cudaFuncAttributeMaxDynamicSharedMemorySize,
                         SMEM_TOTAL);
    prep_wt<<<1024, 256>>>((const float*)d_in[4], (const float*)d_in[8]);
    gcn_hmma<<<BNK_ / 2, NT, SMEM_TOTAL>>>(
        (const float*)d_in[0],   // rep
        (const float*)d_in[1],   // adj_mask_in
        (const float*)d_in[2],   // adj_mask_loop
        (const float*)d_in[3],   // mask
        (const float*)d_in[5],   // b_in
        (const float*)d_in[7],   // b_gate_in
        (const float*)d_in[6],   // W_gate_in
        (const float*)d_in[9],   // W_gate_self
        (const int*)d_in[10],    // adj_arc_in
        (const int*)d_in[11],    // adj_lab_in
        (float*)d_out);
}

// round 15
// speedup vs baseline: 1.1148x; 1.1148x over previous
#include <cuda_runtime.h>
#include <cstdint>

// GCN layer via mma.sync tf32 (HMMA): N-half phases, merged dual-GEMM,
// 3-stage cp.async pipeline, one barrier per chunk, explicit register
// double-buffering of ldmatrix fragments (ks+1 prefetch over ks MMAs).
// A operands: raw fp32 bits (HW tf32 truncation). B: rna-rounded in prepass.
// CTA = 128 rows (2 sentences), 256 threads, 8 warps (2M x 4N).
// Phase p (cols p*128..+127): warp tile 64x32 DUAL (P_in + P_self).

#define BNK_   1280
#define L_     64
#define DIN_   512
#define DOUT_  256
#define KC     32
#define NCHUNK 16

typedef unsigned int u32;

// Pre-transposed, tf32-rounded, SW128-swizzled W: [which][chunk][n=256][k=32]
__device__ float WT_sw[2][NCHUNK][DOUT_][KC];

// ---- SMEM byte offsets ----
#define OFF_GIN  0
#define OFF_GSF  512
#define OFF_WIN  1024
#define OFF_WSF  1536
#define OFF_MKV  2048
#define OFF_GLI  2560
#define OFF_LRI  3072
#define OFF_STG  4096
#define STG_STRIDE 49152          // A 16K + Bi 16K + Bs 16K
#define OFF_PIN  (OFF_STG + 3 * STG_STRIDE)    // 151552
#define SMEM_TOTAL (OFF_PIN + 65536)           // 217088

__device__ __forceinline__ u32 smem_u32(const void* p) {
    u32 a;
    asm("{ .reg .u64 t; cvta.to.shared.u64 t, %1; cvt.u32.u64 %0, t; }"
        : "=r"(a) : "l"(p));
    return a;
}
__device__ __forceinline__ void cpa16(u32 dst, const void* src) {
    asm volatile("cp.async.cg.shared.global [%0], [%1], 16;\n"
                 :: "r"(dst), "l"(src));
}

// A operands passed as raw u32 bits (tf32 = truncated fp32 in HW)
#define MMA8U(d, A, B0, B1)                                                   \
    asm volatile(                                                             \
        "mma.sync.aligned.m16n8k8.row.col.f32.tf32.tf32.f32 "                 \
        "{%0,%1,%2,%3}, {%4,%5,%6,%7}, {%8,%9}, {%0,%1,%2,%3};"               \
        : "+f"((d)[0]), "+f"((d)[1]), "+f"((d)[2]), "+f"((d)[3])              \
        : "r"((A)[0]), "r"((A)[1]), "r"((A)[2]), "r"((A)[3]),                 \
          "r"(B0), "r"(B1))

#define LDMX4(x0, x1, x2, x3, addr)                                           \
    asm volatile(                                                             \
        "ldmatrix.sync.aligned.m8n8.x4.shared.b16 {%0,%1,%2,%3}, [%4];"       \
        : "=r"(x0), "=r"(x1), "=r"(x2), "=r"(x3) : "r"(addr))

// -------------------- prepass: transpose + tf32-round W ---------------------
extern "C" __global__ void prep_wt(const float* __restrict__ W_in,
                                   const float* __restrict__ W_self)
{
    int idx = blockIdx.x * 256 + threadIdx.x;   // 0 .. 262143
    int which = idx >> 17;
    int rem = idx & 131071;
    int k = rem >> 8;        // 0..511 (coalesced reads over n)
    int n = rem & 255;
    const float* W = which ? W_self : W_in;
    float v = W[k * DOUT_ + n];
    asm("cvt.rna.tf32.f32 %0, %1;" : "=f"(v) : "f"(v));
    int c = k >> 5, kk = k & 31;
    int byte = n * 128 + kk * 4;
    int sw = byte ^ ((byte >> 3) & 0x70);
    *(float*)((char*)&WT_sw[which][c][0][0] + sw) = v;
}

// ------------------------------- main kernel --------------------------------
extern "C" __global__ void __launch_bounds__(256, 1)
gcn_hmma(const float* __restrict__ rep,
         const float* __restrict__ adj_mask_in,
         const float* __restrict__ adj_mask_loop,
         const float* __restrict__ mask,
         const float* __restrict__ b_in,
         const float* __restrict__ bg_in,
         const float* __restrict__ Wg_in,
         const float* __restrict__ Wg_self,
         const int* __restrict__ arc,
         const int* __restrict__ lab,
         float* __restrict__ out)
{
    extern __shared__ char smem[];
    const u32 sb = smem_u32(smem);
    const int tid = threadIdx.x;
    const int ln = tid & 31;
    const int wid = tid >> 5;
    const int wm = wid >> 2;     // 0..1  (M half: 64 rows)
    const int wn = wid & 3;      // 0..3  (N quarter of 128: 32 cols)
    const int g = ln >> 2;
    const int t = ln & 3;
    const int m0 = blockIdx.x * 128;

    // ldmatrix lane-address components
    const int rowA = wm * 64 + (ln & 7) + ((ln >> 3) & 1) * 8;   // + mt*16
    const int koffA = ((ln >> 4) & 1) * 16;
    const int rowB = wn * 32 + ((ln >> 4) & 1) * 8 + (ln & 7);   // + nt2*16
    const int koffB = ((ln >> 3) & 1) * 16;

    // precomputed cp.async A-destination (swizzled) offsets: 1024 float4
    int arow[4], asw[4], aq[4];
#pragma unroll
    for (int i = 0; i < 4; i++) {
        int idx = tid + 256 * i;
        arow[i] = idx >> 3;
        aq[i] = idx & 7;
        int b = arow[i] * 128 + aq[i] * 16;
        asw[i] = b ^ ((b >> 3) & 0x70);
    }

    // ch = global chunk 0..31; phase = ch>>4 selects N-half; kc = ch&15
#define LOAD_CHUNK(ch)                                                         \
    do {                                                                       \
        int kc_ = (ch) & 15, p_ = (ch) >> 4;                                   \
        u32 stg = sb + OFF_STG + ((ch) % 3) * STG_STRIDE;                      \
        const char* ab = (const char*)rep + (size_t)m0 * 2048 + kc_ * 128;     \
        _Pragma("unroll")                                                      \
        for (int i = 0; i < 4; i++)                                            \
            cpa16(stg + asw[i], ab + (size_t)arow[i] * 2048 + aq[i] * 16);     \
        const char* bi = (const char*)WT_sw + (size_t)kc_ * 32768              \
                       + p_ * 16384;                                           \
        const char* bs = bi + (size_t)NCHUNK * 32768;                          \
        _Pragma("unroll")                                                      \
        for (int i = 0; i < 4; i++) {                                          \
            int o = (tid + 256 * i) * 16;                                      \
            cpa16(stg + 16384 + o, bi + o);                                    \
            cpa16(stg + 32768 + o, bs + o);                                    \
        }                                                                      \
        asm volatile("cp.async.commit_group;\n" ::: "memory");                 \
    } while (0)

    // fragment load into buffer buf for k-step ksv (current chunk bases)
#define LOAD_FRAGS(ksv, buf)                                                   \
    do {                                                                       \
        int ks_ = (ksv);                                                       \
        _Pragma("unroll")                                                      \
        for (int mt = 0; mt < 4; mt++) {                                       \
            int byte = (rowA + mt * 16) * 128 + ks_ * 32 + koffA;              \
            byte ^= (byte >> 3) & 0x70;                                        \
            LDMX4(fa[buf][mt][0], fa[buf][mt][1],                              \
                  fa[buf][mt][2], fa[buf][mt][3], aBase + byte);               \
        }                                                                      \
        _Pragma("unroll")                                                      \
        for (int n2 = 0; n2 < 2; n2++) {                                       \
            int byte = (rowB + n2 * 16) * 128 + ks_ * 32 + koffB;              \
            byte ^= (byte >> 3) & 0x70;                                        \
            LDMX4(fb[buf][n2][0], fb[buf][n2][1],                              \
                  fb[buf][n2][2], fb[buf][n2][3], biBase + byte);              \
            LDMX4(fe[buf][n2][0], fe[buf][n2][1],                              \
                  fe[buf][n2][2], fe[buf][n2][3], bsBase + byte);              \
        }                                                                      \
    } while (0)

    // prologue: chunks 0,1
    LOAD_CHUNK(0);
    LOAD_CHUNK(1);

    // ---------------- gate GEMVs (full fp32), overlap prologue --------------
    {
        int row = tid >> 1, half = tid & 1;  // 128 rows x 2 K-halves
        const float4* rp = (const float4*)(rep + (size_t)(m0 + row) * DIN_ + half * 256);
        const float4* gi = (const float4*)(Wg_in + half * 256);
        const float4* gs = (const float4*)(Wg_self + half * 256);
        float ai = 0.f, as = 0.f;
#pragma unroll 8
        for (int q = 0; q < 64; q++) {
            float4 v = rp[q], wi = gi[q], ws = gs[q];
            ai += v.x * wi.x + v.y * wi.y + v.z * wi.z + v.w * wi.w;
            as += v.x * ws.x + v.y * ws.y + v.z * ws.z + v.w * ws.w;
        }
        ai += __shfl_xor_sync(0xffffffffu, ai, 1);
        as += __shfl_xor_sync(0xffffffffu, as, 1);
        if (!half) {
            ((float*)(smem + OFF_GIN))[row] = ai;
            ((float*)(smem + OFF_GSF))[row] = as;
        }
    }

    float acc_in[4][4][4];   // [mt][nt(n8 within 32 cols)][quad]
    float acc_sf[4][4][4];
#pragma unroll
    for (int mt = 0; mt < 4; mt++)
#pragma unroll
        for (int nt = 0; nt < 4; nt++)
#pragma unroll
            for (int q = 0; q < 4; q++) { acc_in[mt][nt][q] = 0.f; acc_sf[mt][nt][q] = 0.f; }

    u32 fa[2][4][4];   // A fragments, double-buffered
    u32 fb[2][2][4];   // B_in fragments
    u32 fe[2][2][4];   // B_self fragments

    // ------------------------------ main loop -------------------------------
    // iter c: wait(group c), sync, issue load c+2, compute c with ks+1
    // fragment prefetch overlapping ks MMAs.
#pragma unroll 1
    for (int c = 0; c < 32; c++) {
        if (c < 31)
            asm volatile("cp.async.wait_group 1;" ::: "memory");
        else
            asm volatile("cp.async.wait_group 0;" ::: "memory");
        __syncthreads();

        if (c < 30) LOAD_CHUNK(c + 2);

        const u32 stg = sb + OFF_STG + (c % 3) * STG_STRIDE;
        const u32 aBase = stg, biBase = stg + 16384, bsBase = stg + 32768;

        LOAD_FRAGS(0, 0);
#pragma unroll
        for (int ks = 0; ks < 4; ks++) {
            const int cur = ks & 1;
            if (ks < 3) LOAD_FRAGS(ks + 1, cur ^ 1);
#pragma unroll
            for (int nt2 = 0; nt2 < 2; nt2++) {
#pragma unroll
                for (int mt = 0; mt < 4; mt++) {
                    MMA8U(acc_in[mt][2 * nt2],     fa[cur][mt], fb[cur][nt2][0], fb[cur][nt2][1]);
                    MMA8U(acc_sf[mt][2 * nt2],     fa[cur][mt], fe[cur][nt2][0], fe[cur][nt2][1]);
                    MMA8U(acc_in[mt][2 * nt2 + 1], fa[cur][mt], fb[cur][nt2][2], fb[cur][nt2][3]);
                    MMA8U(acc_sf[mt][2 * nt2 + 1], fa[cur][mt], fe[cur][nt2][2], fe[cur][nt2][3]);
                }
            }
        }

        // ---------------- per-phase epilogue at c == 15 / 31 -----------------
        if ((c & 15) == 15) {
            const int p = c >> 4;
            const int cbase = p * 128;
            // stash P_in half-tile (128 x 128) to swizzled SMEM (own cells)
#pragma unroll
            for (int mt = 0; mt < 4; mt++)
#pragma unroll
                for (int nt = 0; nt < 4; nt++)
#pragma unroll
                    for (int h = 0; h < 2; h++) {
                        int r = wm * 64 + mt * 16 + g + h * 8;
                        int cc4 = (wn * 32 + nt * 8 + 2 * t) * 4;
                        u32 ad = sb + OFF_PIN + r * 512 + (cc4 ^ ((r & 7) << 4));
                        asm volatile("st.shared.v2.f32 [%0], {%1,%2};"
                                     :: "r"(ad), "f"(acc_in[mt][nt][2 * h]),
                                        "f"(acc_in[mt][nt][2 * h + 1]) : "memory");
                    }
            if (p == 0 && tid < 128) {   // per-row params, once
                int r = tid, m = m0 + r;
                int lr = lab[m];
                int gl = (arc[2 * m] * L_ + arc[2 * m + 1]) - m0;
                gl &= 127;
                float mi = adj_mask_in[m], mlp = adj_mask_loop[m];
                float giv = ((float*)(smem + OFF_GIN))[gl] + bg_in[lr];
                float gsv = ((float*)(smem + OFF_GSF))[r];
                ((float*)(smem + OFF_WIN))[r] = (1.f / (1.f + expf(-giv))) * mi * mi;
                ((float*)(smem + OFF_WSF))[r] = (1.f / (1.f + expf(-gsv))) * mlp * mlp;
                ((float*)(smem + OFF_MKV))[r] = mask[m];
                ((int*)(smem + OFF_GLI))[r] = gl;
                ((int*)(smem + OFF_LRI))[r] = lr;
            }
            __syncthreads();

            // combine: gather + gates + relu + store for this column half
#pragma unroll
            for (int mt = 0; mt < 4; mt++)
#pragma unroll
                for (int h = 0; h < 2; h++) {
                    int r = wm * 64 + mt * 16 + g + h * 8;
                    float w_in = ((float*)(smem + OFF_WIN))[r];
                    float w_sf = ((float*)(smem + OFF_WSF))[r];
                    float mkr = ((float*)(smem + OFF_MKV))[r];
                    int gl = ((int*)(smem + OFF_GLI))[r];
                    int lr = ((int*)(smem + OFF_LRI))[r];
                    const u32 pinrow = sb + OFF_PIN + gl * 512;
                    const int xr = (gl & 7) << 4;
                    const float* bb = b_in + lr * DOUT_ + cbase;
                    float* op = out + (size_t)(m0 + r) * DOUT_ + cbase;
#pragma unroll
                    for (int nt = 0; nt < 4; nt++) {
                        int cc = wn * 32 + nt * 8 + 2 * t;
                        float px, py;
                        asm volatile("ld.shared.v2.f32 {%0,%1}, [%2];"
                                     : "=f"(px), "=f"(py)
                                     : "r"(pinrow + ((cc * 4) ^ xr)));
                        float2 bv = *(const float2*)(bb + cc);
                        float2 o;
                        o.x = fmaxf((px + bv.x) * w_in + acc_sf[mt][nt][2 * h] * w_sf, 0.f) * mkr;
                        o.y = fmaxf((py + bv.y) * w_in + acc_sf[mt][nt][2 * h + 1] * w_sf, 0.f) * mkr;
                        *(float2*)(op + cc) = o;
                    }
                }

            if (p == 0) {  // reset accumulators for second half
#pragma unroll
                for (int mt = 0; mt < 4; mt++)
#pragma unroll
                    for (int nt = 0; nt < 4; nt++)
#pragma unroll
                        for (int q = 0; q < 4; q++) {
                            acc_in[mt][nt][q] = 0.f;
                            acc_sf[mt][nt][q] = 0.f;
                        }
            }
        }
    }
}

extern "C" void kernel_launch(void* const* d_in, const int* in_sizes, int n_in,
                              void* d_out, int out_size)
{
    (void)in_sizes; (void)n_in; (void)out_size;
    cudaFuncSetAttribute(gcn_hmma, cudaFuncAttributeMaxDynamicSharedMemorySize,
                         SMEM_TOTAL);
    prep_wt<<<1024, 256>>>((const float*)d_in[4], (const float*)d_in[8]);
    gcn_hmma<<<BNK_ / 2, 256, SMEM_TOTAL>>>(
        (const float*)d_in[0],   // rep
        (const float*)d_in[1],   // adj_mask_in
        (const float*)d_in[2],   // adj_mask_loop
        (const float*)d_in[3],   // mask
        (const float*)d_in[5],   // b_in
        (const float*)d_in[7],   // b_gate_in
        (const float*)d_in[6],   // W_gate_in
        (const float*)d_in[9],   // W_gate_self
        (const int*)d_in[10],    // adj_arc_in
        (const int*)d_in[11],    // adj_lab_in
        (float*)d_out);
}

// round 16
// speedup vs baseline: 1.2190x; 1.0935x over previous
#include <cuda_runtime.h>
#include <cstdint>

// GCN layer via mma.sync tf32 (HMMA): N-half phases, merged dual-GEMM.
// KC=64 chunks (16 barriers), A-only SMEM staging (2 stages), BOTH B
// matrices consumed via fragment-order __ldg from L2-resident buffers.
// A operands: raw fp32 bits (HW tf32 truncation). B: rna-rounded in prepass.
// CTA = 128 rows (2 sentences), 256 threads, 8 warps (2M x 4N).
// Phase p (cols p*128..+127): warp tile 64x32 DUAL (P_in + P_self).

#define BNK_   1280
#define L_     64
#define DIN_   512
#define DOUT_  256

typedef unsigned int u32;

// Fragment-order B: [which][kc32 0..15][j(n16) 0..15][ks 0..3][lane 0..31]
// comp0 = B[kc*32+ks*8+(l&3)][j*16+(l>>2)], comp1 = +k4, comp2/3 = n+8.
__device__ float4 BF[2][16][16][4][32];

// ---- SMEM byte offsets ----
#define OFF_GIN  0
#define OFF_GSF  512
#define OFF_WIN  1024
#define OFF_WSF  1536
#define OFF_MKV  2048
#define OFF_GLI  2560
#define OFF_LRI  3072
#define OFF_STG  4096
#define STG_STRIDE 32768          // A: two 16KB k32 blocks
#define OFF_PIN  (OFF_STG + 2 * STG_STRIDE)    // 69632
#define SMEM_TOTAL (OFF_PIN + 65536)           // 135168

__device__ __forceinline__ u32 smem_u32(const void* p) {
    u32 a;
    asm("{ .reg .u64 t; cvta.to.shared.u64 t, %1; cvt.u32.u64 %0, t; }"
        : "=r"(a) : "l"(p));
    return a;
}
__device__ __forceinline__ void cpa16(u32 dst, const void* src) {
    asm volatile("cp.async.cg.shared.global [%0], [%1], 16;\n"
                 :: "r"(dst), "l"(src));
}

// A operands passed as raw u32 bits (tf32 = truncated fp32 in HW)
#define MMA8U(d, A, B0, B1)                                                   \
    asm volatile(                                                             \
        "mma.sync.aligned.m16n8k8.row.col.f32.tf32.tf32.f32 "                 \
        "{%0,%1,%2,%3}, {%4,%5,%6,%7}, {%8,%9}, {%0,%1,%2,%3};"               \
        : "+f"((d)[0]), "+f"((d)[1]), "+f"((d)[2]), "+f"((d)[3])              \
        : "r"((A)[0]), "r"((A)[1]), "r"((A)[2]), "r"((A)[3]),                 \
          "r"(B0), "r"(B1))

#define LDMX4(x0, x1, x2, x3, addr)                                           \
    asm volatile(                                                             \
        "ldmatrix.sync.aligned.m8n8.x4.shared.b16 {%0,%1,%2,%3}, [%4];"       \
        : "=r"(x0), "=r"(x1), "=r"(x2), "=r"(x3) : "r"(addr))

// -------------------- prepass: tf32-round W into fragment order -------------
extern "C" __global__ void prep_wt(const float* __restrict__ W_in,
                                   const float* __restrict__ W_self)
{
    int idx = blockIdx.x * 256 + threadIdx.x;   // 0 .. 262143
    int which = idx >> 17;
    int rem = idx & 131071;
    int f4 = rem >> 2, comp = rem & 3;
    int kc = f4 >> 11;
    int r1 = f4 & 2047;
    int j = r1 >> 7;
    int r2 = r1 & 127;
    int ks = r2 >> 5;
    int l = r2 & 31;
    int n = j * 16 + ((comp >> 1) << 3) + (l >> 2);
    int k = kc * 32 + ks * 8 + ((comp & 1) << 2) + (l & 3);
    const float* W = which ? W_self : W_in;
    float v = W[k * DOUT_ + n];
    asm("cvt.rna.tf32.f32 %0, %1;" : "=f"(v) : "f"(v));
    ((float*)BF)[which * 131072 + rem] = v;
}

// ------------------------------- main kernel --------------------------------
extern "C" __global__ void __launch_bounds__(256, 1)
gcn_hmma(const float* __restrict__ rep,
         const float* __restrict__ adj_mask_in,
         const float* __restrict__ adj_mask_loop,
         const float* __restrict__ mask,
         const float* __restrict__ b_in,
         const float* __restrict__ bg_in,
         const float* __restrict__ Wg_in,
         const float* __restrict__ Wg_self,
         const int* __restrict__ arc,
         const int* __restrict__ lab,
         float* __restrict__ out)
{
    extern __shared__ char smem[];
    const u32 sb = smem_u32(smem);
    const int tid = threadIdx.x;
    const int ln = tid & 31;
    const int wid = tid >> 5;
    const int wm = wid >> 2;     // 0..1  (M half: 64 rows)
    const int wn = wid & 3;      // 0..3  (N quarter of 128: 32 cols)
    const int g = ln >> 2;
    const int t = ln & 3;
    const int m0 = blockIdx.x * 128;

    // ldmatrix lane-address components (A only)
    const int rowA = wm * 64 + (ln & 7) + ((ln >> 3) & 1) * 8;   // + mt*16
    const int koffA = ((ln >> 4) & 1) * 16;

    // precomputed cp.async A offsets: 2048 float4 per chunk (two k32 blocks)
    int dsto[8], srco[8];
#pragma unroll
    for (int i = 0; i < 8; i++) {
        int idx = tid + 256 * i;
        int blk = idx >> 10;
        int local = idx & 1023;
        int row = local >> 3;
        int q = local & 7;
        int b = row * 128 + q * 16;
        dsto[i] = blk * 16384 + (b ^ ((b >> 3) & 0x70));
        srco[i] = row * 2048 + blk * 128 + q * 16;
    }

    // ch = chunk 0..15 (KC=64); phase = ch>>3; k-pair = (ch&7)*2,+1
#define LOAD_CHUNK(ch)                                                         \
    do {                                                                       \
        u32 stg = sb + OFF_STG + ((ch) & 1) * STG_STRIDE;                      \
        const char* ab = (const char*)rep + (size_t)m0 * 2048                  \
                       + ((ch) & 7) * 256;                                     \
        _Pragma("unroll")                                                      \
        for (int i = 0; i < 8; i++)                                            \
            cpa16(stg + dsto[i], ab + srco[i]);                                \
        asm volatile("cp.async.commit_group;\n" ::: "memory");                 \
    } while (0)

    // prologue: chunk 0
    LOAD_CHUNK(0);

    // ---------------- gate GEMVs (full fp32), overlap prologue --------------
    {
        int row = tid >> 1, half = tid & 1;  // 128 rows x 2 K-halves
        const float4* rp = (const float4*)(rep + (size_t)(m0 + row) * DIN_ + half * 256);
        const float4* gi = (const float4*)(Wg_in + half * 256);
        const float4* gs = (const float4*)(Wg_self + half * 256);
        float ai = 0.f, as = 0.f;
#pragma unroll 8
        for (int q = 0; q < 64; q++) {
            float4 v = rp[q], wi = gi[q], ws = gs[q];
            ai += v.x * wi.x + v.y * wi.y + v.z * wi.z + v.w * wi.w;
            as += v.x * ws.x + v.y * ws.y + v.z * ws.z + v.w * ws.w;
        }
        ai += __shfl_xor_sync(0xffffffffu, ai, 1);
        as += __shfl_xor_sync(0xffffffffu, as, 1);
        if (!half) {
            ((float*)(smem + OFF_GIN))[row] = ai;
            ((float*)(smem + OFF_GSF))[row] = as;
        }
    }

    float acc_in[4][4][4];   // [mt][nt(n8 within 32 cols)][quad]
    float acc_sf[4][4][4];
#pragma unroll
    for (int mt = 0; mt < 4; mt++)
#pragma unroll
        for (int nt = 0; nt < 4; nt++)
#pragma unroll
            for (int q = 0; q < 4; q++) { acc_in[mt][nt][q] = 0.f; acc_sf[mt][nt][q] = 0.f; }

    const float4* bf0 = (const float4*)BF;            // W_in
    const float4* bf1 = (const float4*)BF + 32768;    // W_self

    // ------------------------------ main loop -------------------------------
    // iter c: wait load c, sync, issue load c+1, compute c (two k32 blocks).
#pragma unroll 1
    for (int c = 0; c < 16; c++) {
        asm volatile("cp.async.wait_group 0;" ::: "memory");
        __syncthreads();
        if (c < 15) LOAD_CHUNK(c + 1);

        const int p = c >> 3;
        const int j0 = p * 8 + wn * 2;
        const u32 stg = sb + OFF_STG + (c & 1) * STG_STRIDE;

#pragma unroll
        for (int blk = 0; blk < 2; blk++) {
            const u32 aBase = stg + blk * 16384;
            const int kc = (c & 7) * 2 + blk;
            const float4* bin = bf0 + (size_t)(kc * 16 + j0) * 128 + ln;
            const float4* bsf = bf1 + (size_t)(kc * 16 + j0) * 128 + ln;
#pragma unroll
            for (int ks = 0; ks < 4; ks++) {
                u32 a[4][4];   // raw fp32 bits -> HW tf32 truncation
#pragma unroll
                for (int mt = 0; mt < 4; mt++) {
                    int byte = (rowA + mt * 16) * 128 + ks * 32 + koffA;
                    byte ^= (byte >> 3) & 0x70;
                    LDMX4(a[mt][0], a[mt][1], a[mt][2], a[mt][3], aBase + byte);
                }
#pragma unroll
                for (int nt2 = 0; nt2 < 2; nt2++) {
                    float4 ei = __ldg(bin + nt2 * 128 + ks * 32);
                    float4 es = __ldg(bsf + nt2 * 128 + ks * 32);
                    u32 b0 = __float_as_uint(ei.x), b1 = __float_as_uint(ei.y);
                    u32 b2 = __float_as_uint(ei.z), b3 = __float_as_uint(ei.w);
                    u32 e0 = __float_as_uint(es.x), e1 = __float_as_uint(es.y);
                    u32 e2 = __float_as_uint(es.z), e3 = __float_as_uint(es.w);
#pragma unroll
                    for (int mt = 0; mt < 4; mt++) {
                        MMA8U(acc_in[mt][2 * nt2],     a[mt], b0, b1);
                        MMA8U(acc_sf[mt][2 * nt2],     a[mt], e0, e1);
                        MMA8U(acc_in[mt][2 * nt2 + 1], a[mt], b2, b3);
                        MMA8U(acc_sf[mt][2 * nt2 + 1], a[mt], e2, e3);
                    }
                }
            }
        }

        // ---------------- per-phase epilogue at c == 7 / 15 ------------------
        if ((c & 7) == 7) {
            const int cbase = p * 128;
            // stash P_in half-tile (128 x 128) to swizzled SMEM (own cells)
#pragma unroll
            for (int mt = 0; mt < 4; mt++)
#pragma unroll
                for (int nt = 0; nt < 4; nt++)
#pragma unroll
                    for (int h = 0; h < 2; h++) {
                        int r = wm * 64 + mt * 16 + g + h * 8;
                        int cc4 = (wn * 32 + nt * 8 + 2 * t) * 4;
                        u32 ad = sb + OFF_PIN + r * 512 + (cc4 ^ ((r & 7) << 4));
                        asm volatile("st.shared.v2.f32 [%0], {%1,%2};"
                                     :: "r"(ad), "f"(acc_in[mt][nt][2 * h]),
                                        "f"(acc_in[mt][nt][2 * h + 1]) : "memory");
                    }
            if (p == 0 && tid < 128) {   // per-row params, once
                int r = tid, m = m0 + r;
                int lr = lab[m];
                int gl = (arc[2 * m] * L_ + arc[2 * m + 1]) - m0;
                gl &= 127;
                float mi = adj_mask_in[m], mlp = adj_mask_loop[m];
                float giv = ((float*)(smem + OFF_GIN))[gl] + bg_in[lr];
                float gsv = ((float*)(smem + OFF_GSF))[r];
                ((float*)(smem + OFF_WIN))[r] = (1.f / (1.f + expf(-giv))) * mi * mi;
                ((float*)(smem + OFF_WSF))[r] = (1.f / (1.f + expf(-gsv))) * mlp * mlp;
                ((float*)(smem + OFF_MKV))[r] = mask[m];
                ((int*)(smem + OFF_GLI))[r] = gl;
                ((int*)(smem + OFF_LRI))[r] = lr;
            }
            __syncthreads();

            // combine: gather + gates + relu + store for this column half
#pragma unroll
            for (int mt = 0; mt < 4; mt++)
#pragma unroll
                for (int h = 0; h < 2; h++) {
                    int r = wm * 64 + mt * 16 + g + h * 8;
                    float w_in = ((float*)(smem + OFF_WIN))[r];
                    float w_sf = ((float*)(smem + OFF_WSF))[r];
                    float mkr = ((float*)(smem + OFF_MKV))[r];
                    int gl = ((int*)(smem + OFF_GLI))[r];
                    int lr = ((int*)(smem + OFF_LRI))[r];
                    const u32 pinrow = sb + OFF_PIN + gl * 512;
                    const int xr = (gl & 7) << 4;
                    const float* bb = b_in + lr * DOUT_ + cbase;
                    float* op = out + (size_t)(m0 + r) * DOUT_ + cbase;
#pragma unroll
                    for (int nt = 0; nt < 4; nt++) {
                        int cc = wn * 32 + nt * 8 + 2 * t;
                        float px, py;
                        asm volatile("ld.shared.v2.f32 {%0,%1}, [%2];"
                                     : "=f"(px), "=f"(py)
                                     : "r"(pinrow + ((cc * 4) ^ xr)));
                        float2 bv = *(const float2*)(bb + cc);
                        float2 o;
                        o.x = fmaxf((px + bv.x) * w_in + acc_sf[mt][nt][2 * h] * w_sf, 0.f) * mkr;
                        o.y = fmaxf((py + bv.y) * w_in + acc_sf[mt][nt][2 * h + 1] * w_sf, 0.f) * mkr;
                        *(float2*)(op + cc) = o;
                    }
                }

            if (p == 0) {  // reset accumulators for second half
#pragma unroll
                for (int mt = 0; mt < 4; mt++)
#pragma unroll
                    for (int nt = 0; nt < 4; nt++)
#pragma unroll
                        for (int q = 0; q < 4; q++) {
                            acc_in[mt][nt][q] = 0.f;
                            acc_sf[mt][nt][q] = 0.f;
                        }
            }
        }
    }
}

extern "C" void kernel_launch(void* const* d_in, const int* in_sizes, int n_in,
                              void* d_out, int out_size)
{
    (void)in_sizes; (void)n_in; (void)out_size;
    cudaFuncSetAttribute(gcn_hmma, cudaFuncAttributeMaxDynamicSharedMemorySize,
                         SMEM_TOTAL);
    prep_wt<<<1024, 256>>>((const float*)d_in[4], (const float*)d_in[8]);
    gcn_hmma<<<BNK_ / 2, 256, SMEM_TOTAL>>>(
        (const float*)d_in[0],   // rep
        (const float*)d_in[1],   // adj_mask_in
        (const float*)d_in[2],   // adj_mask_loop
        (const float*)d_in[3],   // mask
        (const float*)d_in[5],   // b_in
        (const float*)d_in[7],   // b_gate_in
        (const float*)d_in[6],   // W_gate_in
        (const float*)d_in[9],   // W_gate_self
        (const int*)d_in[10],    // adj_arc_in
        (const int*)d_in[11],    // adj_lab_in
        (float*)d_out);
}

// round 17
// speedup vs baseline: 1.3995x; 1.1481x over previous
#include <cuda_runtime.h>
#include <cstdint>

// GCN layer via mma.sync fp16 m16n8k16 (HMMA): N-half phases, merged
// dual-GEMM, KC=64 chunks (16 barriers), A-only SMEM staging (fp16, 2
// stages), both B matrices via fragment-order __ldg uint4 (L2-resident).
// rep converted to fp16 by prepass (84MB device buffer); gates in fp32.
// CTA = 128 rows (2 sentences), 256 threads, 8 warps (2M x 4N).
// Phase p (cols p*128..+127): warp tile 64x32 DUAL (P_in + P_self).

#define BNK_   1280
#define L_     64
#define DIN_   512
#define DOUT_  256

typedef unsigned int u32;

// rep in fp16, row-major [81920][512]
__device__ __align__(16) unsigned short REP_H[(size_t)BNK_ * L_ * DIN_];
// Fragment-order fp16 B: [which][kc16 0..31][j2(n16) 0..15][lane 0..31]
//   x = {W[k0+2t][n0+g], W[k0+2t+1][n0+g]}   (k0=kc*16, n0=j2*16, g=l>>2,t=l&3)
//   y = {+k8, +k9}, z/w = same at n0+8+g.
__device__ uint4 BFH[2 * 32 * 16 * 32];

// ---- SMEM byte offsets ----
#define OFF_GIN  0
#define OFF_GSF  512
#define OFF_WIN  1024
#define OFF_WSF  1536
#define OFF_MKV  2048
#define OFF_GLI  2560
#define OFF_LRI  3072
#define OFF_STG  4096
#define STG_STRIDE 16384          // A chunk: 128 rows x 64 fp16 = 16KB
#define OFF_PIN  (OFF_STG + 2 * STG_STRIDE)    // 36864
#define SMEM_TOTAL (OFF_PIN + 65536)           // 102400

__device__ __forceinline__ u32 smem_u32(const void* p) {
    u32 a;
    asm("{ .reg .u64 t; cvta.to.shared.u64 t, %1; cvt.u32.u64 %0, t; }"
        : "=r"(a) : "l"(p));
    return a;
}
__device__ __forceinline__ void cpa16(u32 dst, const void* src) {
    asm volatile("cp.async.cg.shared.global [%0], [%1], 16;\n"
                 :: "r"(dst), "l"(src));
}
__device__ __forceinline__ u32 f2h2(float hi, float lo) {
    u32 h;
    asm("cvt.rn.f16x2.f32 %0, %1, %2;" : "=r"(h) : "f"(hi), "f"(lo));
    return h;
}

#define MMA16H(d, A, B0, B1)                                                  \
    asm volatile(                                                             \
        "mma.sync.aligned.m16n8k16.row.col.f32.f16.f16.f32 "                  \
        "{%0,%1,%2,%3}, {%4,%5,%6,%7}, {%8,%9}, {%0,%1,%2,%3};"               \
        : "+f"((d)[0]), "+f"((d)[1]), "+f"((d)[2]), "+f"((d)[3])              \
        : "r"((A)[0]), "r"((A)[1]), "r"((A)[2]), "r"((A)[3]),                 \
          "r"(B0), "r"(B1))

#define LDMX4(x0, x1, x2, x3, addr)                                           \
    asm volatile(                                                             \
        "ldmatrix.sync.aligned.m8n8.x4.shared.b16 {%0,%1,%2,%3}, [%4];"       \
        : "=r"(x0), "=r"(x1), "=r"(x2), "=r"(x3) : "r"(addr))

// ---------------- prepass 1: rep fp32 -> fp16 (coalesced) --------------------
extern "C" __global__ void prep_rep(const float* __restrict__ rep)
{
    size_t idx = (size_t)blockIdx.x * 256 + threadIdx.x;  // 0 .. 5242879
    const float4* src = (const float4*)rep + idx * 2;
    float4 v0 = src[0], v1 = src[1];
    uint4 o;
    o.x = f2h2(v0.y, v0.x);
    o.y = f2h2(v0.w, v0.z);
    o.z = f2h2(v1.y, v1.x);
    o.w = f2h2(v1.w, v1.z);
    ((uint4*)REP_H)[idx] = o;
}

// ---------------- prepass 2: W -> fp16 fragment order ------------------------
extern "C" __global__ void prep_wt(const float* __restrict__ W_in,
                                   const float* __restrict__ W_self)
{
    int idx = blockIdx.x * 256 + threadIdx.x;   // 0 .. 32767
    int which = idx >> 14;
    int rem = idx & 16383;
    int kc = rem >> 9;
    int r1 = rem & 511;
    int j2 = r1 >> 5;
    int l = r1 & 31;
    int g = l >> 2, t = l & 3;
    const float* W = which ? W_self : W_in;
    int k0 = kc * 16 + 2 * t, n0 = j2 * 16 + g;
    uint4 o;
    o.x = f2h2(W[(k0 + 1) * DOUT_ + n0],     W[k0 * DOUT_ + n0]);
    o.y = f2h2(W[(k0 + 9) * DOUT_ + n0],     W[(k0 + 8) * DOUT_ + n0]);
    o.z = f2h2(W[(k0 + 1) * DOUT_ + n0 + 8], W[k0 * DOUT_ + n0 + 8]);
    o.w = f2h2(W[(k0 + 9) * DOUT_ + n0 + 8], W[(k0 + 8) * DOUT_ + n0 + 8]);
    BFH[idx] = o;
}

// ------------------------------- main kernel --------------------------------
extern "C" __global__ void __launch_bounds__(256, 1)
gcn_hmma(const float* __restrict__ rep,
         const float* __restrict__ adj_mask_in,
         const float* __restrict__ adj_mask_loop,
         const float* __restrict__ mask,
         const float* __restrict__ b_in,
         const float* __restrict__ bg_in,
         const float* __restrict__ Wg_in,
         const float* __restrict__ Wg_self,
         const int* __restrict__ arc,
         const int* __restrict__ lab,
         float* __restrict__ out)
{
    extern __shared__ char smem[];
    const u32 sb = smem_u32(smem);
    const int tid = threadIdx.x;
    const int ln = tid & 31;
    const int wid = tid >> 5;
    const int wm = wid >> 2;     // 0..1  (M half: 64 rows)
    const int wn = wid & 3;      // 0..3  (N quarter of 128: 32 cols)
    const int g = ln >> 2;
    const int t = ln & 3;
    const int m0 = blockIdx.x * 128;

    // ldmatrix lane-address components (A only); rows 128B apart (64 fp16)
    const int rowA = wm * 64 + (ln & 7) + ((ln >> 3) & 1) * 8;   // + mt*16
    const int koffA = ((ln >> 4) & 1) * 16;

    // precomputed cp.async A offsets: 1024 float4 per 16KB chunk
    int dsto[4], srco[4];
#pragma unroll
    for (int i = 0; i < 4; i++) {
        int idx = tid + 256 * i;
        int row = idx >> 3;
        int q = idx & 7;
        int b = row * 128 + q * 16;
        dsto[i] = b ^ ((b >> 3) & 0x70);
        srco[i] = row * 1024 + q * 16;   // REP_H row stride = 1024 B
    }

    // ch = chunk 0..15 (K64 each); phase = ch>>3; K window = (ch&7)*64
#define LOAD_CHUNK(ch)                                                         \
    do {                                                                       \
        u32 stg = sb + OFF_STG + ((ch) & 1) * STG_STRIDE;                      \
        const char* ab = (const char*)REP_H + (size_t)m0 * 1024                \
                       + ((ch) & 7) * 128;                                     \
        _Pragma("unroll")                                                      \
        for (int i = 0; i < 4; i++)                                            \
            cpa16(stg + dsto[i], ab + srco[i]);                                \
        asm volatile("cp.async.commit_group;\n" ::: "memory");                 \
    } while (0)

    // prologue: chunk 0
    LOAD_CHUNK(0);

    // ---------------- gate GEMVs (full fp32), overlap prologue --------------
    {
        int row = tid >> 1, half = tid & 1;  // 128 rows x 2 K-halves
        const float4* rp = (const float4*)(rep + (size_t)(m0 + row) * DIN_ + half * 256);
        const float4* gi = (const float4*)(Wg_in + half * 256);
        const float4* gs = (const float4*)(Wg_self + half * 256);
        float ai = 0.f, as = 0.f;
#pragma unroll 8
        for (int q = 0; q < 64; q++) {
            float4 v = rp[q], wi = gi[q], ws = gs[q];
            ai += v.x * wi.x + v.y * wi.y + v.z * wi.z + v.w * wi.w;
            as += v.x * ws.x + v.y * ws.y + v.z * ws.z + v.w * ws.w;
        }
        ai += __shfl_xor_sync(0xffffffffu, ai, 1);
        as += __shfl_xor_sync(0xffffffffu, as, 1);
        if (!half) {
            ((float*)(smem + OFF_GIN))[row] = ai;
            ((float*)(smem + OFF_GSF))[row] = as;
        }
    }

    float acc_in[4][4][4];   // [mt][nt(n8 within 32 cols)][quad]
    float acc_sf[4][4][4];
#pragma unroll
    for (int mt = 0; mt < 4; mt++)
#pragma unroll
        for (int nt = 0; nt < 4; nt++)
#pragma unroll
            for (int q = 0; q < 4; q++) { acc_in[mt][nt][q] = 0.f; acc_sf[mt][nt][q] = 0.f; }

    const uint4* bfi = BFH;             // W_in fragments
    const uint4* bfs = BFH + 16384;     // W_self fragments

    // ------------------------------ main loop -------------------------------
    // iter c: wait load c, sync, issue load c+1, compute c (4 k16 groups).
#pragma unroll 1
    for (int c = 0; c < 16; c++) {
        asm volatile("cp.async.wait_group 0;" ::: "memory");
        __syncthreads();
        if (c < 15) LOAD_CHUNK(c + 1);

        const int p = c >> 3;
        const u32 aBase = sb + OFF_STG + (c & 1) * STG_STRIDE;

#pragma unroll
        for (int ks = 0; ks < 4; ks++) {
            const int kc = (c & 7) * 4 + ks;     // global k16 index 0..31
            u32 a[4][4];
#pragma unroll
            for (int mt = 0; mt < 4; mt++) {
                int byte = (rowA + mt * 16) * 128 + ks * 32 + koffA;
                byte ^= (byte >> 3) & 0x70;
                LDMX4(a[mt][0], a[mt][1], a[mt][2], a[mt][3], aBase + byte);
            }
#pragma unroll
            for (int jj = 0; jj < 2; jj++) {
                const int j2g = p * 8 + wn * 2 + jj;   // global n16 group
                uint4 vi = __ldg(bfi + ((kc * 16 + j2g) << 5) + ln);
                uint4 vs = __ldg(bfs + ((kc * 16 + j2g) << 5) + ln);
#pragma unroll
                for (int mt = 0; mt < 4; mt++) {
                    MMA16H(acc_in[mt][jj * 2],     a[mt], vi.x, vi.y);
                    MMA16H(acc_sf[mt][jj * 2],     a[mt], vs.x, vs.y);
                    MMA16H(acc_in[mt][jj * 2 + 1], a[mt], vi.z, vi.w);
                    MMA16H(acc_sf[mt][jj * 2 + 1], a[mt], vs.z, vs.w);
                }
            }
        }

        // ---------------- per-phase epilogue at c == 7 / 15 ------------------
        if ((c & 7) == 7) {
            const int cbase = p * 128;
            // stash P_in half-tile (128 x 128) to swizzled SMEM (own cells)
#pragma unroll
            for (int mt = 0; mt < 4; mt++)
#pragma unroll
                for (int nt = 0; nt < 4; nt++)
#pragma unroll
                    for (int h = 0; h < 2; h++) {
                        int r = wm * 64 + mt * 16 + g + h * 8;
                        int cc4 = (wn * 32 + nt * 8 + 2 * t) * 4;
                        u32 ad = sb + OFF_PIN + r * 512 + (cc4 ^ ((r & 7) << 4));
                        asm volatile("st.shared.v2.f32 [%0], {%1,%2};"
                                     :: "r"(ad), "f"(acc_in[mt][nt][2 * h]),
                                        "f"(acc_in[mt][nt][2 * h + 1]) : "memory");
                    }
            if (p == 0 && tid < 128) {   // per-row params, once
                int r = tid, m = m0 + r;
                int lr = lab[m];
                int gl = (arc[2 * m] * L_ + arc[2 * m + 1]) - m0;
                gl &= 127;
                float mi = adj_mask_in[m], mlp = adj_mask_loop[m];
                float giv = ((float*)(smem + OFF_GIN))[gl] + bg_in[lr];
                float gsv = ((float*)(smem + OFF_GSF))[r];
                ((float*)(smem + OFF_WIN))[r] = (1.f / (1.f + expf(-giv))) * mi * mi;
                ((float*)(smem + OFF_WSF))[r] = (1.f / (1.f + expf(-gsv))) * mlp * mlp;
                ((float*)(smem + OFF_MKV))[r] = mask[m];
                ((int*)(smem + OFF_GLI))[r] = gl;
                ((int*)(smem + OFF_LRI))[r] = lr;
            }
            __syncthreads();

            // combine: gather + gates + relu + store for this column half
#pragma unroll
            for (int mt = 0; mt < 4; mt++)
#pragma unroll
                for (int h = 0; h < 2; h++) {
                    int r = wm * 64 + mt * 16 + g + h * 8;
                    float w_in = ((float*)(smem + OFF_WIN))[r];
                    float w_sf = ((float*)(smem + OFF_WSF))[r];
                    float mkr = ((float*)(smem + OFF_MKV))[r];
                    int gl = ((int*)(smem + OFF_GLI))[r];
                    int lr = ((int*)(smem + OFF_LRI))[r];
                    const u32 pinrow = sb + OFF_PIN + gl * 512;
                    const int xr = (gl & 7) << 4;
                    const float* bb = b_in + lr * DOUT_ + cbase;
                    float* op = out + (size_t)(m0 + r) * DOUT_ + cbase;
#pragma unroll
                    for (int nt = 0; nt < 4; nt++) {
                        int cc = wn * 32 + nt * 8 + 2 * t;
                        float px, py;
                        asm volatile("ld.shared.v2.f32 {%0,%1}, [%2];"
                                     : "=f"(px), "=f"(py)
                                     : "r"(pinrow + ((cc * 4) ^ xr)));
                        float2 bv = *(const float2*)(bb + cc);
                        float2 o;
                        o.x = fmaxf((px + bv.x) * w_in + acc_sf[mt][nt][2 * h] * w_sf, 0.f) * mkr;
                        o.y = fmaxf((py + bv.y) * w_in + acc_sf[mt][nt][2 * h + 1] * w_sf, 0.f) * mkr;
                        *(float2*)(op + cc) = o;
                    }
                }

            if (p == 0) {  // reset accumulators for second half
#pragma unroll
                for (int mt = 0; mt < 4; mt++)
#pragma unroll
                    for (int nt = 0; nt < 4; nt++)
#pragma unroll
                        for (int q = 0; q < 4; q++) {
                            acc_in[mt][nt][q] = 0.f;
                            acc_sf[mt][nt][q] = 0.f;
                        }
            }
        }
    }
}

extern "C" void kernel_launch(void* const* d_in, const int* in_sizes, int n_in,
                              void* d_out, int out_size)
{
    (void)in_sizes; (void)n_in; (void)out_size;
    cudaFuncSetAttribute(gcn_hmma, cudaFuncAttributeMaxDynamicSharedMemorySize,
                         SMEM_TOTAL);
    prep_rep<<<20480, 256>>>((const float*)d_in[0]);
    prep_wt<<<128, 256>>>((const float*)d_in[4], (const float*)d_in[8]);
    gcn_hmma<<<BNK_ / 2, 256, SMEM_TOTAL>>>(
        (const float*)d_in[0],   // rep
        (const float*)d_in[1],   // adj_mask_in
        (const float*)d_in[2],   // adj_mask_loop
        (const float*)d_in[3],   // mask
        (const float*)d_in[5],   // b_in
        (const float*)d_in[7],   // b_gate_in
        (const float*)d_in[6],   // W_gate_in
        (const float*)d_in[9],   // W_gate_self
        (const int*)d_in[10],    // adj_arc_in
        (const int*)d_in[11],    // adj_lab_in
        (float*)d_out);
}